// round 15
// baseline (speedup 1.0000x reference)
#include <cuda_runtime.h>
#include <cuda_fp16.h>
#include <math.h>
#include <stdint.h>

#define NN 100000
#define EE 1600000
#define FIN 100

typedef unsigned long long ull;

// ---------------- scratch (static device allocations) ----------------
__device__ float g_bufA[NN * 128];
__device__ __align__(16) __half g_p0[NN * 256];
__device__ __align__(16) __half g_p1[NN * 256];
__device__ int   g_deg[NN];
__device__ int   g_incl[NN];
__device__ int   g_rowptr[NN + 1];
__device__ int   g_cursor[NN];
__device__ __align__(8) uint2 g_edge[EE];   // {src, norm(fp32 bits)}
__device__ float g_dinv[NN];
__device__ int   g_part[128];
__device__ float g_bnsum[256];
// transposed fp16 weights, [Npad][Kpad]
__device__ __align__(16) __half g_w1h[128 * 128];
__device__ __align__(16) __half g_w2h[128 * 128];
__device__ __align__(16) __half g_w3h[256 * 128];
__device__ __align__(16) __half g_f1h[256 * 256];
__device__ __align__(16) __half g_f2h[128 * 256];

// ---------------- PTX helpers ----------------
__device__ __forceinline__ uint32_t smem_u32(const void* p) {
    uint32_t a;
    asm("{ .reg .u64 t; cvta.to.shared.u64 t, %1; cvt.u32.u64 %0, t; }" : "=r"(a) : "l"(p));
    return a;
}
__device__ __forceinline__ void ldsm4(uint32_t addr, uint32_t* r) {
    asm volatile("ldmatrix.sync.aligned.m8n8.x4.shared.b16 {%0,%1,%2,%3}, [%4];"
                 : "=r"(r[0]), "=r"(r[1]), "=r"(r[2]), "=r"(r[3]) : "r"(addr));
}
__device__ __forceinline__ void mma16816(float* d, const uint32_t* a, const uint32_t* b) {
    asm volatile(
        "mma.sync.aligned.m16n8k16.row.col.f32.f16.f16.f32 "
        "{%0,%1,%2,%3}, {%4,%5,%6,%7}, {%8,%9}, {%0,%1,%2,%3};"
        : "+f"(d[0]), "+f"(d[1]), "+f"(d[2]), "+f"(d[3])
        : "r"(a[0]), "r"(a[1]), "r"(a[2]), "r"(a[3]), "r"(b[0]), "r"(b[1]));
}
__device__ __forceinline__ void cp16(uint32_t s, const void* g) {
    asm volatile("cp.async.cg.shared.global [%0], [%1], 16;" :: "r"(s), "l"(g));
}
__device__ __forceinline__ void cp16z(uint32_t s, const void* g, int srcsz) {
    asm volatile("cp.async.cg.shared.global [%0], [%1], 16, %2;" :: "r"(s), "l"(g), "r"(srcsz));
}
#define CP_COMMIT() asm volatile("cp.async.commit_group;" ::: "memory")
#define CP_WAIT(n)  asm volatile("cp.async.wait_group %0;" :: "n"(n) : "memory")

__device__ __forceinline__ uint32_t pack_h2(float a, float b) {
    __half2 h = __floats2half2_rn(a, b);
    return *reinterpret_cast<uint32_t*>(&h);
}

// ---------------- CSR build ----------------
__global__ void k_zero() {
    int i = blockIdx.x * blockDim.x + threadIdx.x;
    if (i < NN) g_deg[i] = 0;
    if (i < 256) g_bnsum[i] = 0.0f;
}
__global__ void k_count(const int* __restrict__ dst) {
    int e = blockIdx.x * blockDim.x + threadIdx.x;
    if (e < EE) atomicAdd(&g_deg[dst[e]], 1);
}
__global__ void k_scan1() {
    __shared__ int sh[1024];
    int i = blockIdx.x * 1024 + threadIdx.x;
    int v = (i < NN) ? g_deg[i] : 0;
    sh[threadIdx.x] = v;
    __syncthreads();
    for (int off = 1; off < 1024; off <<= 1) {
        int t = (threadIdx.x >= (unsigned)off) ? sh[threadIdx.x - off] : 0;
        __syncthreads();
        sh[threadIdx.x] += t;
        __syncthreads();
    }
    if (i < NN) g_incl[i] = sh[threadIdx.x];
    if (threadIdx.x == 1023) g_part[blockIdx.x] = sh[1023];
}
// rowptr with in-block scan of the 98 block partials (replaces k_scan2)
__global__ void k_rowptr(int nb) {
    __shared__ int sp[128];
    int t = threadIdx.x;
    if (t < 128) sp[t] = (t < nb) ? g_part[t] : 0;
    __syncthreads();
    #pragma unroll
    for (int off = 1; off < 128; off <<= 1) {
        int v = (t < 128 && t >= off) ? sp[t - off] : 0;
        __syncthreads();
        if (t < 128) sp[t] += v;
        __syncthreads();
    }
    int i = blockIdx.x * blockDim.x + t;
    if (i >= NN) return;
    int b = i >> 10;
    int off = (b == 0) ? 0 : sp[b - 1];
    int excl = g_incl[i] - g_deg[i] + off;
    g_rowptr[i] = excl;
    g_cursor[i] = excl;
    g_dinv[i] = rsqrtf((float)g_deg[i] + 1.0f);
    if (i == NN - 1) g_rowptr[NN] = g_incl[i] + off;
}
__global__ void k_fill(const int* __restrict__ src, const int* __restrict__ dst) {
    int e = blockIdx.x * blockDim.x + threadIdx.x;
    if (e >= EE) return;
    int s = src[e], d = dst[e];
    int p = atomicAdd(&g_cursor[d], 1);
    float nr = __ldg(&g_dinv[s]) * __ldg(&g_dinv[d]);
    g_edge[p] = make_uint2((uint32_t)s, __float_as_uint(nr));
}

// -------- agg pass 1: fp32 x input, clip inline, fp16 out [.,128] ------------
__global__ void k_aggbf(const float* __restrict__ in, __half* __restrict__ oh) {
    int gw = (blockIdx.x * blockDim.x + threadIdx.x) >> 5;
    if (gw >= NN) return;
    int lane = threadIdx.x & 31;
    bool act = lane < 25;
    int c4 = lane << 2;
    float di = g_dinv[gw];
    int s0 = g_rowptr[gw], s1 = g_rowptr[gw + 1];
    float a0 = 0.f, a1 = 0.f, a2 = 0.f, a3 = 0.f;
    float b0 = 0.f, b1 = 0.f, b2 = 0.f, b3 = 0.f;
    float c0 = 0.f, c1 = 0.f, c2 = 0.f, c3 = 0.f;
    float d0 = 0.f, d1 = 0.f, d2 = 0.f, d3 = 0.f;
    int e = s0;
    for (; e + 3 < s1; e += 4) {
        uint2 e0 = __ldg(&g_edge[e]);
        uint2 e1 = __ldg(&g_edge[e + 1]);
        uint2 e2 = __ldg(&g_edge[e + 2]);
        uint2 e3 = __ldg(&g_edge[e + 3]);
        if (act) {
            float4 v0 = __ldg((const float4*)(in + (size_t)e0.x * FIN + c4));
            float4 v1 = __ldg((const float4*)(in + (size_t)e1.x * FIN + c4));
            float4 v2 = __ldg((const float4*)(in + (size_t)e2.x * FIN + c4));
            float4 v3 = __ldg((const float4*)(in + (size_t)e3.x * FIN + c4));
            float n0 = __uint_as_float(e0.y), n1 = __uint_as_float(e1.y);
            float n2 = __uint_as_float(e2.y), n3 = __uint_as_float(e3.y);
            a0 += n0 * fminf(fmaxf(v0.x, -0.4f), 0.4f);
            a1 += n0 * fminf(fmaxf(v0.y, -0.4f), 0.4f);
            a2 += n0 * fminf(fmaxf(v0.z, -0.4f), 0.4f);
            a3 += n0 * fminf(fmaxf(v0.w, -0.4f), 0.4f);
            b0 += n1 * fminf(fmaxf(v1.x, -0.4f), 0.4f);
            b1 += n1 * fminf(fmaxf(v1.y, -0.4f), 0.4f);
            b2 += n1 * fminf(fmaxf(v1.z, -0.4f), 0.4f);
            b3 += n1 * fminf(fmaxf(v1.w, -0.4f), 0.4f);
            c0 += n2 * fminf(fmaxf(v2.x, -0.4f), 0.4f);
            c1 += n2 * fminf(fmaxf(v2.y, -0.4f), 0.4f);
            c2 += n2 * fminf(fmaxf(v2.z, -0.4f), 0.4f);
            c3 += n2 * fminf(fmaxf(v2.w, -0.4f), 0.4f);
            d0 += n3 * fminf(fmaxf(v3.x, -0.4f), 0.4f);
            d1 += n3 * fminf(fmaxf(v3.y, -0.4f), 0.4f);
            d2 += n3 * fminf(fmaxf(v3.z, -0.4f), 0.4f);
            d3 += n3 * fminf(fmaxf(v3.w, -0.4f), 0.4f);
        }
    }
    for (; e < s1; e++) {
        uint2 e0 = __ldg(&g_edge[e]);
        if (act) {
            float4 v = __ldg((const float4*)(in + (size_t)e0.x * FIN + c4));
            float n0 = __uint_as_float(e0.y);
            a0 += n0 * fminf(fmaxf(v.x, -0.4f), 0.4f);
            a1 += n0 * fminf(fmaxf(v.y, -0.4f), 0.4f);
            a2 += n0 * fminf(fmaxf(v.z, -0.4f), 0.4f);
            a3 += n0 * fminf(fmaxf(v.w, -0.4f), 0.4f);
        }
    }
    if (act) {   // self loop
        float nn = di * di;
        float4 v = *(const float4*)(in + (size_t)gw * FIN + c4);
        a0 += nn * fminf(fmaxf(v.x, -0.4f), 0.4f);
        a1 += nn * fminf(fmaxf(v.y, -0.4f), 0.4f);
        a2 += nn * fminf(fmaxf(v.z, -0.4f), 0.4f);
        a3 += nn * fminf(fmaxf(v.w, -0.4f), 0.4f);
    }
    a0 += b0 + c0 + d0; a1 += b1 + c1 + d1;
    a2 += b2 + c2 + d2; a3 += b3 + c3 + d3;
    uint2 ph = {0u, 0u};
    if (act) { ph.x = pack_h2(a0, a1); ph.y = pack_h2(a2, a3); }
    ((uint2*)oh)[((size_t)gw << 5) + lane] = ph;
}

// -------- agg passes 2,3: fp16 in [.,128] -> fp16 out, packed edges ----------
__global__ void k_agg16(const __half* __restrict__ in, __half* __restrict__ oh) {
    int gw = (blockIdx.x * blockDim.x + threadIdx.x) >> 5;
    if (gw >= NN) return;
    int lane = threadIdx.x & 31;
    bool act = lane < 25;
    float di = g_dinv[gw];
    int s0 = g_rowptr[gw], s1 = g_rowptr[gw + 1];
    float a0 = 0.f, a1 = 0.f, a2 = 0.f, a3 = 0.f;
    float b0 = 0.f, b1 = 0.f, b2 = 0.f, b3 = 0.f;
    float c0 = 0.f, c1 = 0.f, c2 = 0.f, c3 = 0.f;
    float d0 = 0.f, d1 = 0.f, d2 = 0.f, d3 = 0.f;
    const uint2* inv = (const uint2*)in;
    int e = s0;
    for (; e + 3 < s1; e += 4) {
        uint2 e0 = __ldg(&g_edge[e]);
        uint2 e1 = __ldg(&g_edge[e + 1]);
        uint2 e2 = __ldg(&g_edge[e + 2]);
        uint2 e3 = __ldg(&g_edge[e + 3]);
        if (act) {
            uint2 u0 = __ldg(inv + ((size_t)e0.x << 5) + lane);
            uint2 u1 = __ldg(inv + ((size_t)e1.x << 5) + lane);
            uint2 u2 = __ldg(inv + ((size_t)e2.x << 5) + lane);
            uint2 u3 = __ldg(inv + ((size_t)e3.x << 5) + lane);
            float n0 = __uint_as_float(e0.y), n1 = __uint_as_float(e1.y);
            float n2 = __uint_as_float(e2.y), n3 = __uint_as_float(e3.y);
            float2 f;
            f = __half22float2(*(__half2*)&u0.x); a0 += n0 * f.x; a1 += n0 * f.y;
            f = __half22float2(*(__half2*)&u0.y); a2 += n0 * f.x; a3 += n0 * f.y;
            f = __half22float2(*(__half2*)&u1.x); b0 += n1 * f.x; b1 += n1 * f.y;
            f = __half22float2(*(__half2*)&u1.y); b2 += n1 * f.x; b3 += n1 * f.y;
            f = __half22float2(*(__half2*)&u2.x); c0 += n2 * f.x; c1 += n2 * f.y;
            f = __half22float2(*(__half2*)&u2.y); c2 += n2 * f.x; c3 += n2 * f.y;
            f = __half22float2(*(__half2*)&u3.x); d0 += n3 * f.x; d1 += n3 * f.y;
            f = __half22float2(*(__half2*)&u3.y); d2 += n3 * f.x; d3 += n3 * f.y;
        }
    }
    for (; e < s1; e++) {
        uint2 e0 = __ldg(&g_edge[e]);
        if (act) {
            uint2 u0 = __ldg(inv + ((size_t)e0.x << 5) + lane);
            float n0 = __uint_as_float(e0.y);
            float2 f;
            f = __half22float2(*(__half2*)&u0.x); a0 += n0 * f.x; a1 += n0 * f.y;
            f = __half22float2(*(__half2*)&u0.y); a2 += n0 * f.x; a3 += n0 * f.y;
        }
    }
    if (act) {   // self loop
        float nn = di * di;
        uint2 u = *(inv + ((size_t)gw << 5) + lane);
        float2 f0 = __half22float2(*(__half2*)&u.x);
        float2 f1 = __half22float2(*(__half2*)&u.y);
        a0 += nn * f0.x; a1 += nn * f0.y; a2 += nn * f1.x; a3 += nn * f1.y;
    }
    a0 += b0 + c0 + d0; a1 += b1 + c1 + d1;
    a2 += b2 + c2 + d2; a3 += b3 + c3 + d3;
    uint2 ph = {0u, 0u};
    if (act) { ph.x = pack_h2(a0, a1); ph.y = pack_h2(a2, a3); }
    ((uint2*)oh)[((size_t)gw << 5) + lane] = ph;
}

// ------- combined weight prep: 5 segments, single fp16 output ----------------
__global__ void k_prep_all(const float* W1, const float* W2, const float* W3,
                           const float* F1, const float* F2,
                           __half* w1h, __half* w2h, __half* w3h,
                           __half* f1h, __half* f2h) {
    int seg = blockIdx.y;
    const float* W; __half* Th;
    int K, Nw, Kpad, Npad;
    switch (seg) {
        case 0: W = W1; Th = w1h; K = 100; Nw = 100; Kpad = 128; Npad = 128; break;
        case 1: W = W2; Th = w2h; K = 100; Nw = 100; Kpad = 128; Npad = 128; break;
        case 2: W = W3; Th = w3h; K = 100; Nw = 256; Kpad = 128; Npad = 256; break;
        case 3: W = F1; Th = f1h; K = 256; Nw = 256; Kpad = 256; Npad = 256; break;
        default: W = F2; Th = f2h; K = 256; Nw = 128; Kpad = 256; Npad = 128; break;
    }
    int total = Npad * Kpad;
    for (int idx = blockIdx.x * blockDim.x + threadIdx.x; idx < total; idx += gridDim.x * blockDim.x) {
        int n = idx / Kpad, k = idx % Kpad;
        float v = (k < K && n < Nw) ? W[(size_t)k * Nw + n] : 0.f;
        Th[idx] = __float2half_rn(v);
    }
}

// ------- mma.sync fp16 GEMM, single product: C = act(A @ W + bias) ----------
#define LDW 20
#define CHB (128 * LDW * 4)
#define BUFB (2 * CHB)

template <int BNACC>
__global__ void __launch_bounds__(256, 2)
k_mma(const __half* __restrict__ A, const __half* __restrict__ Bh,
      const float* __restrict__ bias,
      float* __restrict__ C, __half* __restrict__ Ch,
      int M, int Kpad, int Nc, int ldc, int relu, int outmode) {
    extern __shared__ uint32_t sm[];
    uint32_t sbase = smem_u32(sm);

    int tid = threadIdx.x;
    int wid = tid >> 5, lane = tid & 31;
    int br = blockIdx.y * 128;
    int bc = blockIdx.x * 128;
    int wm = (wid & 3) * 32;
    int wn = (wid >> 2) * 64;

    int srow[2], sg[2];
    uint32_t soff[2];
    #pragma unroll
    for (int j = 0; j < 2; j++) {
        int idx = tid + (j << 8);
        srow[j] = idx >> 2; sg[j] = idx & 3;
        soff[j] = (uint32_t)(srow[j] * LDW + (sg[j] << 2)) * 4;
    }

    uint32_t aOff[2], bOff[4];
    #pragma unroll
    for (int mt = 0; mt < 2; mt++)
        aOff[mt] = ((wm + mt * 16 + (lane & 15)) * 40 + ((lane >> 4) << 3)) * 2;
    #pragma unroll
    for (int ng = 0; ng < 4; ng++)
        bOff[ng] = ((wn + ng * 16 + (lane & 7) + ((lane >> 4) << 3)) * 40 + (((lane >> 3) & 1) << 3)) * 2;

    float acc[2][8][4];
    #pragma unroll
    for (int i = 0; i < 2; i++)
        #pragma unroll
        for (int j = 0; j < 8; j++)
            #pragma unroll
            for (int p = 0; p < 4; p++) acc[i][j][p] = 0.f;

    int nkc = Kpad >> 5;

    auto stage = [&](int kc, int buf) {
        int k0 = kc << 5;
        uint32_t b0 = sbase + buf * BUFB;
        #pragma unroll
        for (int j = 0; j < 2; j++) {
            int gm = br + srow[j];
            int ok = (gm < M);
            size_t ga = ((size_t)(ok ? gm : 0) * Kpad + k0) * 2 + (sg[j] << 4);
            cp16z(b0 + soff[j], (const char*)A + ga, ok ? 16 : 0);
            size_t gb = ((size_t)(bc + srow[j]) * Kpad + k0) * 2 + (sg[j] << 4);
            cp16(b0 + CHB + soff[j], (const char*)Bh + gb);
        }
    };

    stage(0, 0);
    CP_COMMIT();

    for (int kc = 0; kc < nkc; kc++) {
        int buf = kc & 1;
        if (kc + 1 < nkc) {
            stage(kc + 1, buf ^ 1);
            CP_COMMIT();
            CP_WAIT(1);
        } else {
            CP_WAIT(0);
        }
        __syncthreads();

        uint32_t aBase = sbase + buf * BUFB;
        uint32_t bBase = aBase + CHB;

        #pragma unroll
        for (int kk = 0; kk < 32; kk += 16) {
            uint32_t aF[2][4], bb[8][2];
            #pragma unroll
            for (int mt = 0; mt < 2; mt++) ldsm4(aBase + aOff[mt] + kk * 2, aF[mt]);
            #pragma unroll
            for (int ng = 0; ng < 4; ng++) ldsm4(bBase + bOff[ng] + kk * 2, &bb[2 * ng][0]);
            #pragma unroll
            for (int mt = 0; mt < 2; mt++)
                #pragma unroll
                for (int nt = 0; nt < 8; nt++) mma16816(acc[mt][nt], aF[mt], bb[nt]);
        }
        __syncthreads();
    }

    float sC[8][2], sQ[8][2];
    if (BNACC) {
        #pragma unroll
        for (int nt = 0; nt < 8; nt++) { sC[nt][0] = sC[nt][1] = sQ[nt][0] = sQ[nt][1] = 0.f; }
    }

    // ---- epilogue ----
    #pragma unroll
    for (int mt = 0; mt < 2; mt++) {
        int r0 = br + wm + mt * 16 + (lane >> 2);
        #pragma unroll
        for (int nt = 0; nt < 8; nt++) {
            int gn = bc + wn + nt * 8 + ((lane & 3) << 1);
            float bv0 = (gn < Nc) ? bias[gn] : 0.f;
            float bv1 = (gn + 1 < Nc) ? bias[gn + 1] : 0.f;
            float c0 = acc[mt][nt][0] + bv0, c1 = acc[mt][nt][1] + bv1;
            float c2 = acc[mt][nt][2] + bv0, c3 = acc[mt][nt][3] + bv1;
            if (relu) {
                c0 = fmaxf(c0, 0.f); c1 = fmaxf(c1, 0.f);
                c2 = fmaxf(c2, 0.f); c3 = fmaxf(c3, 0.f);
            }
            if (BNACC) {
                float v0 = (r0 < M) ? c0 : 0.f, v2 = (r0 + 8 < M) ? c2 : 0.f;
                float v1 = (r0 < M) ? c1 : 0.f, v3 = (r0 + 8 < M) ? c3 : 0.f;
                sC[nt][0] += v0 + v2; sQ[nt][0] += v0 * v0 + v2 * v2;
                sC[nt][1] += v1 + v3; sQ[nt][1] += v1 * v1 + v3 * v3;
            }
            if (outmode == 0) {
                if (gn + 1 < Nc) {
                    if (r0 < M) { float2 v = {c0, c1}; *(float2*)&C[(size_t)r0 * Nc + gn] = v; }
                    if (r0 + 8 < M) { float2 v = {c2, c3}; *(float2*)&C[(size_t)(r0 + 8) * Nc + gn] = v; }
                } else if (gn < Nc) {
                    if (r0 < M) C[(size_t)r0 * Nc + gn] = c0;
                    if (r0 + 8 < M) C[(size_t)(r0 + 8) * Nc + gn] = c2;
                }
            } else {
                if (r0 < M)
                    ((uint32_t*)Ch)[((size_t)r0 * ldc + gn) >> 1] = pack_h2(c0, c1);
                if (r0 + 8 < M)
                    ((uint32_t*)Ch)[((size_t)(r0 + 8) * ldc + gn) >> 1] = pack_h2(c2, c3);
            }
        }
    }

    if (BNACC) {
        #pragma unroll
        for (int nt = 0; nt < 8; nt++) {
            #pragma unroll
            for (int c = 0; c < 2; c++) {
                float s = sC[nt][c], q = sQ[nt][c];
                #pragma unroll
                for (int off = 4; off < 32; off <<= 1) {
                    s += __shfl_xor_sync(0xffffffffu, s, off);
                    q += __shfl_xor_sync(0xffffffffu, q, off);
                }
                if ((lane >> 2) == 0) {
                    int gn = bc + wn + nt * 8 + ((lane & 3) << 1) + c;
                    atomicAdd(&g_bnsum[gn], s);
                    atomicAdd(&g_bnsum[128 + gn], q);
                }
            }
        }
    }
}

// ------- final: BN coef + affine + ReLU + [128x19] GEMV + log_softmax -------
__global__ void k_final_out(const float* __restrict__ z, const float* __restrict__ gamma,
                            const float* __restrict__ beta, const float* __restrict__ W,
                            const float* __restrict__ b, float* __restrict__ out) {
    __shared__ float scoef[256];
    if (threadIdx.x < 128) {
        int c = threadIdx.x;
        float inv = 1.0f / (float)NN;
        float mu = g_bnsum[c] * inv;
        float var = g_bnsum[128 + c] * inv - mu * mu;
        float sc = gamma[c] * rsqrtf(var + 1e-5f);
        scoef[c] = sc;
        scoef[128 + c] = beta[c] - mu * sc;
    }
    __syncthreads();

    int gw = (blockIdx.x * blockDim.x + threadIdx.x) >> 5;
    if (gw >= NN) return;
    int lane = threadIdx.x & 31;
    float h[4];
    #pragma unroll
    for (int u = 0; u < 4; u++) {
        int c = lane + 32 * u;
        float v = z[gw * 128 + c];
        h[u] = fmaxf(v * scoef[c] + scoef[128 + c], 0.f);
    }
    float acc = (lane < 19) ? b[lane] : 0.f;
    #pragma unroll
    for (int u = 0; u < 4; u++) {
        #pragma unroll
        for (int l = 0; l < 32; l++) {
            float hb = __shfl_sync(0xffffffffu, h[u], l);
            if (lane < 19) acc += hb * __ldg(&W[(u * 32 + l) * 19 + lane]);
        }
    }
    float v = (lane < 19) ? acc : -3.4e38f;
    float m = v;
    #pragma unroll
    for (int off = 16; off > 0; off >>= 1) m = fmaxf(m, __shfl_xor_sync(0xffffffffu, m, off));
    float ex = (lane < 19) ? expf(v - m) : 0.f;
    float ssum = ex;
    #pragma unroll
    for (int off = 16; off > 0; off >>= 1) ssum += __shfl_xor_sync(0xffffffffu, ssum, off);
    if (lane < 19) out[gw * 19 + lane] = v - m - logf(ssum);
}

// ---------------------------------------------------------------------------
extern "C" void kernel_launch(void* const* d_in, const int* in_sizes, int n_in,
                              void* d_out, int out_size) {
    const float* x     = (const float*)d_in[0];
    const int*   ei    = (const int*)d_in[1];
    const float* W1    = (const float*)d_in[2];
    const float* b1    = (const float*)d_in[3];
    const float* W2    = (const float*)d_in[4];
    const float* b2    = (const float*)d_in[5];
    const float* W3    = (const float*)d_in[6];
    const float* b3    = (const float*)d_in[7];
    const float* fc1W  = (const float*)d_in[8];
    const float* fc1b  = (const float*)d_in[9];
    const float* fc2aW = (const float*)d_in[10];
    const float* fc2ab = (const float*)d_in[11];
    const float* gamma = (const float*)d_in[12];
    const float* beta  = (const float*)d_in[13];
    const float* fc2bW = (const float*)d_in[14];
    const float* fc2bb = (const float*)d_in[15];
    float* out = (float*)d_out;

    const int* src = ei;
    const int* dst = ei + EE;

    float* bufA;
    cudaGetSymbolAddress((void**)&bufA, g_bufA);
    __half *p0, *p1;
    cudaGetSymbolAddress((void**)&p0, g_p0);
    cudaGetSymbolAddress((void**)&p1, g_p1);
    __half *w1h, *w2h, *w3h, *f1h, *f2h;
    cudaGetSymbolAddress((void**)&w1h, g_w1h);
    cudaGetSymbolAddress((void**)&w2h, g_w2h);
    cudaGetSymbolAddress((void**)&w3h, g_w3h);
    cudaGetSymbolAddress((void**)&f1h, g_f1h);
    cudaGetSymbolAddress((void**)&f2h, g_f2h);

    cudaFuncSetAttribute(k_mma<0>, cudaFuncAttributeMaxDynamicSharedMemorySize, 2 * BUFB);
    cudaFuncSetAttribute(k_mma<1>, cudaFuncAttributeMaxDynamicSharedMemorySize, 2 * BUFB);
    const size_t SMB = 2 * BUFB;   // 40960 bytes

    const int nb = (NN + 1023) / 1024;  // 98

    // CSR build (zeroes g_bnsum too); scan2 folded into rowptr
    k_zero<<<(NN + 255) / 256, 256>>>();
    k_count<<<(EE + 255) / 256, 256>>>(dst);
    k_scan1<<<nb, 1024>>>();
    k_rowptr<<<(NN + 255) / 256, 256>>>(nb);
    k_fill<<<(EE + 255) / 256, 256>>>(src, dst);

    // weight prep (one launch, 5 segments)
    k_prep_all<<<dim3(64, 5), 256>>>(W1, W2, W3, fc1W, fc2aW, w1h, w2h, w3h, f1h, f2h);

    const int aggBlocks = (NN * 32 + 255) / 256;
    const int gy = (NN + 127) / 128;  // 782

    // conv1: agg(fp32 x, clip inline) -> p0 ; mma -> p1 (fp16, ldc=128)
    k_aggbf<<<aggBlocks, 256>>>(x, p0);
    k_mma<0><<<dim3(1, gy), 256, SMB>>>(p0, w1h, b1, 0, p1, NN, 128, 100, 128, 1, 1);
    // conv2
    k_agg16<<<aggBlocks, 256>>>(p1, p0);
    k_mma<0><<<dim3(1, gy), 256, SMB>>>(p0, w2h, b2, 0, p1, NN, 128, 100, 128, 1, 1);
    // conv3 -> p1 (fp16, ldc=256)
    k_agg16<<<aggBlocks, 256>>>(p1, p0);
    k_mma<0><<<dim3(2, gy), 256, SMB>>>(p0, w3h, b3, 0, p1, NN, 128, 256, 256, 1, 1);
    // fc1 -> p0 (fp16, ldc=256)
    k_mma<0><<<dim3(2, gy), 256, SMB>>>(p1, f1h, fc1b, 0, p0, NN, 256, 256, 256, 1, 1);
    // fc2a -> fp32 bufA, fused BN statistics
    k_mma<1><<<dim3(1, gy), 256, SMB>>>(p0, f2h, fc2ab, bufA, 0, NN, 256, 128, 128, 0, 0);
    // final
    k_final_out<<<aggBlocks, 256>>>(bufA, gamma, beta, fc2bW, fc2bb, out);
}

// round 16
// speedup vs baseline: 1.0144x; 1.0144x over previous
#include <cuda_runtime.h>
#include <cuda_fp16.h>
#include <math.h>
#include <stdint.h>

#define NN 100000
#define EE 1600000
#define FIN 100

typedef unsigned long long ull;

// ---------------- scratch (static device allocations) ----------------
__device__ float g_bufA[NN * 128];
__device__ __align__(16) __half g_p0[NN * 256];
__device__ __align__(16) __half g_p1[NN * 256];
__device__ __align__(16) __half g_xh[NN * 128];
__device__ int   g_deg[NN];
__device__ int   g_incl[NN];
__device__ int   g_rowptr[NN + 1];
__device__ int   g_cursor[NN];
__device__ __align__(8) uint2 g_edge[EE];   // {src, norm(fp32 bits)}
__device__ float g_dinv[NN];
__device__ int   g_part[128];
__device__ float g_bnsum[256];
// transposed fp16 weights, [Npad][Kpad]
__device__ __align__(16) __half g_w1h[128 * 128];
__device__ __align__(16) __half g_w2h[128 * 128];
__device__ __align__(16) __half g_w3h[256 * 128];
__device__ __align__(16) __half g_f1h[256 * 256];
__device__ __align__(16) __half g_f2h[128 * 256];

// ---------------- PTX helpers ----------------
__device__ __forceinline__ uint32_t smem_u32(const void* p) {
    uint32_t a;
    asm("{ .reg .u64 t; cvta.to.shared.u64 t, %1; cvt.u32.u64 %0, t; }" : "=r"(a) : "l"(p));
    return a;
}
__device__ __forceinline__ void ldsm4(uint32_t addr, uint32_t* r) {
    asm volatile("ldmatrix.sync.aligned.m8n8.x4.shared.b16 {%0,%1,%2,%3}, [%4];"
                 : "=r"(r[0]), "=r"(r[1]), "=r"(r[2]), "=r"(r[3]) : "r"(addr));
}
__device__ __forceinline__ void mma16816(float* d, const uint32_t* a, const uint32_t* b) {
    asm volatile(
        "mma.sync.aligned.m16n8k16.row.col.f32.f16.f16.f32 "
        "{%0,%1,%2,%3}, {%4,%5,%6,%7}, {%8,%9}, {%0,%1,%2,%3};"
        : "+f"(d[0]), "+f"(d[1]), "+f"(d[2]), "+f"(d[3])
        : "r"(a[0]), "r"(a[1]), "r"(a[2]), "r"(a[3]), "r"(b[0]), "r"(b[1]));
}
__device__ __forceinline__ void cp16(uint32_t s, const void* g) {
    asm volatile("cp.async.cg.shared.global [%0], [%1], 16;" :: "r"(s), "l"(g));
}
__device__ __forceinline__ void cp16z(uint32_t s, const void* g, int srcsz) {
    asm volatile("cp.async.cg.shared.global [%0], [%1], 16, %2;" :: "r"(s), "l"(g), "r"(srcsz));
}
#define CP_COMMIT() asm volatile("cp.async.commit_group;" ::: "memory")
#define CP_WAIT(n)  asm volatile("cp.async.wait_group %0;" :: "n"(n) : "memory")

__device__ __forceinline__ uint32_t pack_h2(float a, float b) {
    __half2 h = __floats2half2_rn(a, b);
    return *reinterpret_cast<uint32_t*>(&h);
}

// ---------------- CSR build ----------------
__global__ void k_zero() {
    int i = blockIdx.x * blockDim.x + threadIdx.x;
    if (i < NN) g_deg[i] = 0;
    if (i < 256) g_bnsum[i] = 0.0f;
}
__global__ void k_count(const int* __restrict__ dst) {
    int e = blockIdx.x * blockDim.x + threadIdx.x;
    if (e < EE) atomicAdd(&g_deg[dst[e]], 1);
}
__global__ void k_scan1() {
    __shared__ int sh[1024];
    int i = blockIdx.x * 1024 + threadIdx.x;
    int v = (i < NN) ? g_deg[i] : 0;
    sh[threadIdx.x] = v;
    __syncthreads();
    for (int off = 1; off < 1024; off <<= 1) {
        int t = (threadIdx.x >= (unsigned)off) ? sh[threadIdx.x - off] : 0;
        __syncthreads();
        sh[threadIdx.x] += t;
        __syncthreads();
    }
    if (i < NN) g_incl[i] = sh[threadIdx.x];
    if (threadIdx.x == 1023) g_part[blockIdx.x] = sh[1023];
}
// rowptr with in-block scan of the 98 block partials (replaces k_scan2)
__global__ void k_rowptr(int nb) {
    __shared__ int sp[128];
    int t = threadIdx.x;
    if (t < 128) sp[t] = (t < nb) ? g_part[t] : 0;
    __syncthreads();
    #pragma unroll
    for (int off = 1; off < 128; off <<= 1) {
        int v = (t < 128 && t >= off) ? sp[t - off] : 0;
        __syncthreads();
        if (t < 128) sp[t] += v;
        __syncthreads();
    }
    int i = blockIdx.x * blockDim.x + t;
    if (i >= NN) return;
    int b = i >> 10;
    int off = (b == 0) ? 0 : sp[b - 1];
    int excl = g_incl[i] - g_deg[i] + off;
    g_rowptr[i] = excl;
    g_cursor[i] = excl;
    g_dinv[i] = rsqrtf((float)g_deg[i] + 1.0f);
    if (i == NN - 1) g_rowptr[NN] = g_incl[i] + off;
}
__global__ void k_fill(const int* __restrict__ src, const int* __restrict__ dst) {
    int e = blockIdx.x * blockDim.x + threadIdx.x;
    if (e >= EE) return;
    int s = src[e], d = dst[e];
    int p = atomicAdd(&g_cursor[d], 1);
    float nr = __ldg(&g_dinv[s]) * __ldg(&g_dinv[d]);
    g_edge[p] = make_uint2((uint32_t)s, __float_as_uint(nr));
}

// ------- prep: 5 weight segments + x-conversion segment (blockIdx.y = 5) -----
__global__ void k_prep_all(const float* W1, const float* W2, const float* W3,
                           const float* F1, const float* F2, const float* x,
                           __half* w1h, __half* w2h, __half* w3h,
                           __half* f1h, __half* f2h, __half* xh) {
    int seg = blockIdx.y;
    if (seg == 5) {
        // x -> clipped fp16, padded to 128
        int w = blockIdx.x * 8 + (threadIdx.x >> 5);
        int lane = threadIdx.x & 31;
        for (int gw = w; gw < NN; gw += gridDim.x * 8) {
            uint2 ph = {0u, 0u};
            if (lane < 25) {
                float4 v = __ldg((const float4*)(x + (size_t)gw * FIN + (lane << 2)));
                v.x = fminf(fmaxf(v.x, -0.4f), 0.4f);
                v.y = fminf(fmaxf(v.y, -0.4f), 0.4f);
                v.z = fminf(fmaxf(v.z, -0.4f), 0.4f);
                v.w = fminf(fmaxf(v.w, -0.4f), 0.4f);
                ph.x = pack_h2(v.x, v.y);
                ph.y = pack_h2(v.z, v.w);
            }
            ((uint2*)xh)[((size_t)gw << 5) + lane] = ph;
        }
        return;
    }
    const float* W; __half* Th;
    int K, Nw, Kpad, Npad;
    switch (seg) {
        case 0: W = W1; Th = w1h; K = 100; Nw = 100; Kpad = 128; Npad = 128; break;
        case 1: W = W2; Th = w2h; K = 100; Nw = 100; Kpad = 128; Npad = 128; break;
        case 2: W = W3; Th = w3h; K = 100; Nw = 256; Kpad = 128; Npad = 256; break;
        case 3: W = F1; Th = f1h; K = 256; Nw = 256; Kpad = 256; Npad = 256; break;
        default: W = F2; Th = f2h; K = 256; Nw = 128; Kpad = 256; Npad = 128; break;
    }
    int total = Npad * Kpad;
    for (int idx = blockIdx.x * blockDim.x + threadIdx.x; idx < total; idx += gridDim.x * blockDim.x) {
        int n = idx / Kpad, k = idx % Kpad;
        float v = (k < K && n < Nw) ? W[(size_t)k * Nw + n] : 0.f;
        Th[idx] = __float2half_rn(v);
    }
}

// -------- aggregation: fp16 in [.,128] -> fp16 out, packed edges -------------
__global__ void k_agg16(const __half* __restrict__ in, __half* __restrict__ oh) {
    int gw = (blockIdx.x * blockDim.x + threadIdx.x) >> 5;
    if (gw >= NN) return;
    int lane = threadIdx.x & 31;
    bool act = lane < 25;
    float di = g_dinv[gw];
    int s0 = g_rowptr[gw], s1 = g_rowptr[gw + 1];
    float a0 = 0.f, a1 = 0.f, a2 = 0.f, a3 = 0.f;
    float b0 = 0.f, b1 = 0.f, b2 = 0.f, b3 = 0.f;
    float c0 = 0.f, c1 = 0.f, c2 = 0.f, c3 = 0.f;
    float d0 = 0.f, d1 = 0.f, d2 = 0.f, d3 = 0.f;
    const uint2* inv = (const uint2*)in;
    int e = s0;
    for (; e + 3 < s1; e += 4) {
        uint2 e0 = __ldg(&g_edge[e]);
        uint2 e1 = __ldg(&g_edge[e + 1]);
        uint2 e2 = __ldg(&g_edge[e + 2]);
        uint2 e3 = __ldg(&g_edge[e + 3]);
        if (act) {
            uint2 u0 = __ldg(inv + ((size_t)e0.x << 5) + lane);
            uint2 u1 = __ldg(inv + ((size_t)e1.x << 5) + lane);
            uint2 u2 = __ldg(inv + ((size_t)e2.x << 5) + lane);
            uint2 u3 = __ldg(inv + ((size_t)e3.x << 5) + lane);
            float n0 = __uint_as_float(e0.y), n1 = __uint_as_float(e1.y);
            float n2 = __uint_as_float(e2.y), n3 = __uint_as_float(e3.y);
            float2 f;
            f = __half22float2(*(__half2*)&u0.x); a0 += n0 * f.x; a1 += n0 * f.y;
            f = __half22float2(*(__half2*)&u0.y); a2 += n0 * f.x; a3 += n0 * f.y;
            f = __half22float2(*(__half2*)&u1.x); b0 += n1 * f.x; b1 += n1 * f.y;
            f = __half22float2(*(__half2*)&u1.y); b2 += n1 * f.x; b3 += n1 * f.y;
            f = __half22float2(*(__half2*)&u2.x); c0 += n2 * f.x; c1 += n2 * f.y;
            f = __half22float2(*(__half2*)&u2.y); c2 += n2 * f.x; c3 += n2 * f.y;
            f = __half22float2(*(__half2*)&u3.x); d0 += n3 * f.x; d1 += n3 * f.y;
            f = __half22float2(*(__half2*)&u3.y); d2 += n3 * f.x; d3 += n3 * f.y;
        }
    }
    for (; e < s1; e++) {
        uint2 e0 = __ldg(&g_edge[e]);
        if (act) {
            uint2 u0 = __ldg(inv + ((size_t)e0.x << 5) + lane);
            float n0 = __uint_as_float(e0.y);
            float2 f;
            f = __half22float2(*(__half2*)&u0.x); a0 += n0 * f.x; a1 += n0 * f.y;
            f = __half22float2(*(__half2*)&u0.y); a2 += n0 * f.x; a3 += n0 * f.y;
        }
    }
    if (act) {   // self loop
        float nn = di * di;
        uint2 u = *(inv + ((size_t)gw << 5) + lane);
        float2 f0 = __half22float2(*(__half2*)&u.x);
        float2 f1 = __half22float2(*(__half2*)&u.y);
        a0 += nn * f0.x; a1 += nn * f0.y; a2 += nn * f1.x; a3 += nn * f1.y;
    }
    a0 += b0 + c0 + d0; a1 += b1 + c1 + d1;
    a2 += b2 + c2 + d2; a3 += b3 + c3 + d3;
    uint2 ph = {0u, 0u};
    if (act) { ph.x = pack_h2(a0, a1); ph.y = pack_h2(a2, a3); }
    ((uint2*)oh)[((size_t)gw << 5) + lane] = ph;
}

// ------- mma.sync fp16 GEMM, single product: C = act(A @ W + bias) ----------
#define LDW 20
#define CHB (128 * LDW * 4)
#define BUFB (2 * CHB)

template <int BNACC>
__global__ void __launch_bounds__(256, 2)
k_mma(const __half* __restrict__ A, const __half* __restrict__ Bh,
      const float* __restrict__ bias,
      float* __restrict__ C, __half* __restrict__ Ch,
      int M, int Kpad, int Nc, int ldc, int relu, int outmode) {
    extern __shared__ uint32_t sm[];
    uint32_t sbase = smem_u32(sm);

    int tid = threadIdx.x;
    int wid = tid >> 5, lane = tid & 31;
    int br = blockIdx.y * 128;
    int bc = blockIdx.x * 128;
    int wm = (wid & 3) * 32;
    int wn = (wid >> 2) * 64;

    int srow[2], sg[2];
    uint32_t soff[2];
    #pragma unroll
    for (int j = 0; j < 2; j++) {
        int idx = tid + (j << 8);
        srow[j] = idx >> 2; sg[j] = idx & 3;
        soff[j] = (uint32_t)(srow[j] * LDW + (sg[j] << 2)) * 4;
    }

    uint32_t aOff[2], bOff[4];
    #pragma unroll
    for (int mt = 0; mt < 2; mt++)
        aOff[mt] = ((wm + mt * 16 + (lane & 15)) * 40 + ((lane >> 4) << 3)) * 2;
    #pragma unroll
    for (int ng = 0; ng < 4; ng++)
        bOff[ng] = ((wn + ng * 16 + (lane & 7) + ((lane >> 4) << 3)) * 40 + (((lane >> 3) & 1) << 3)) * 2;

    float acc[2][8][4];
    #pragma unroll
    for (int i = 0; i < 2; i++)
        #pragma unroll
        for (int j = 0; j < 8; j++)
            #pragma unroll
            for (int p = 0; p < 4; p++) acc[i][j][p] = 0.f;

    int nkc = Kpad >> 5;

    auto stage = [&](int kc, int buf) {
        int k0 = kc << 5;
        uint32_t b0 = sbase + buf * BUFB;
        #pragma unroll
        for (int j = 0; j < 2; j++) {
            int gm = br + srow[j];
            int ok = (gm < M);
            size_t ga = ((size_t)(ok ? gm : 0) * Kpad + k0) * 2 + (sg[j] << 4);
            cp16z(b0 + soff[j], (const char*)A + ga, ok ? 16 : 0);
            size_t gb = ((size_t)(bc + srow[j]) * Kpad + k0) * 2 + (sg[j] << 4);
            cp16(b0 + CHB + soff[j], (const char*)Bh + gb);
        }
    };

    stage(0, 0);
    CP_COMMIT();

    for (int kc = 0; kc < nkc; kc++) {
        int buf = kc & 1;
        if (kc + 1 < nkc) {
            stage(kc + 1, buf ^ 1);
            CP_COMMIT();
            CP_WAIT(1);
        } else {
            CP_WAIT(0);
        }
        __syncthreads();

        uint32_t aBase = sbase + buf * BUFB;
        uint32_t bBase = aBase + CHB;

        #pragma unroll
        for (int kk = 0; kk < 32; kk += 16) {
            uint32_t aF[2][4], bb[8][2];
            #pragma unroll
            for (int mt = 0; mt < 2; mt++) ldsm4(aBase + aOff[mt] + kk * 2, aF[mt]);
            #pragma unroll
            for (int ng = 0; ng < 4; ng++) ldsm4(bBase + bOff[ng] + kk * 2, &bb[2 * ng][0]);
            #pragma unroll
            for (int mt = 0; mt < 2; mt++)
                #pragma unroll
                for (int nt = 0; nt < 8; nt++) mma16816(acc[mt][nt], aF[mt], bb[nt]);
        }
        __syncthreads();
    }

    float sC[8][2], sQ[8][2];
    if (BNACC) {
        #pragma unroll
        for (int nt = 0; nt < 8; nt++) { sC[nt][0] = sC[nt][1] = sQ[nt][0] = sQ[nt][1] = 0.f; }
    }

    // ---- epilogue ----
    #pragma unroll
    for (int mt = 0; mt < 2; mt++) {
        int r0 = br + wm + mt * 16 + (lane >> 2);
        #pragma unroll
        for (int nt = 0; nt < 8; nt++) {
            int gn = bc + wn + nt * 8 + ((lane & 3) << 1);
            float bv0 = (gn < Nc) ? bias[gn] : 0.f;
            float bv1 = (gn + 1 < Nc) ? bias[gn + 1] : 0.f;
            float c0 = acc[mt][nt][0] + bv0, c1 = acc[mt][nt][1] + bv1;
            float c2 = acc[mt][nt][2] + bv0, c3 = acc[mt][nt][3] + bv1;
            if (relu) {
                c0 = fmaxf(c0, 0.f); c1 = fmaxf(c1, 0.f);
                c2 = fmaxf(c2, 0.f); c3 = fmaxf(c3, 0.f);
            }
            if (BNACC) {
                float v0 = (r0 < M) ? c0 : 0.f, v2 = (r0 + 8 < M) ? c2 : 0.f;
                float v1 = (r0 < M) ? c1 : 0.f, v3 = (r0 + 8 < M) ? c3 : 0.f;
                sC[nt][0] += v0 + v2; sQ[nt][0] += v0 * v0 + v2 * v2;
                sC[nt][1] += v1 + v3; sQ[nt][1] += v1 * v1 + v3 * v3;
            }
            if (outmode == 0) {
                if (gn + 1 < Nc) {
                    if (r0 < M) { float2 v = {c0, c1}; *(float2*)&C[(size_t)r0 * Nc + gn] = v; }
                    if (r0 + 8 < M) { float2 v = {c2, c3}; *(float2*)&C[(size_t)(r0 + 8) * Nc + gn] = v; }
                } else if (gn < Nc) {
                    if (r0 < M) C[(size_t)r0 * Nc + gn] = c0;
                    if (r0 + 8 < M) C[(size_t)(r0 + 8) * Nc + gn] = c2;
                }
            } else {
                if (r0 < M)
                    ((uint32_t*)Ch)[((size_t)r0 * ldc + gn) >> 1] = pack_h2(c0, c1);
                if (r0 + 8 < M)
                    ((uint32_t*)Ch)[((size_t)(r0 + 8) * ldc + gn) >> 1] = pack_h2(c2, c3);
            }
        }
    }

    if (BNACC) {
        #pragma unroll
        for (int nt = 0; nt < 8; nt++) {
            #pragma unroll
            for (int c = 0; c < 2; c++) {
                float s = sC[nt][c], q = sQ[nt][c];
                #pragma unroll
                for (int off = 4; off < 32; off <<= 1) {
                    s += __shfl_xor_sync(0xffffffffu, s, off);
                    q += __shfl_xor_sync(0xffffffffu, q, off);
                }
                if ((lane >> 2) == 0) {
                    int gn = bc + wn + nt * 8 + ((lane & 3) << 1) + c;
                    atomicAdd(&g_bnsum[gn], s);
                    atomicAdd(&g_bnsum[128 + gn], q);
                }
            }
        }
    }
}

// ------- final: BN coef + affine + ReLU + [128x19] GEMV + log_softmax -------
__global__ void k_final_out(const float* __restrict__ z, const float* __restrict__ gamma,
                            const float* __restrict__ beta, const float* __restrict__ W,
                            const float* __restrict__ b, float* __restrict__ out) {
    __shared__ float scoef[256];
    if (threadIdx.x < 128) {
        int c = threadIdx.x;
        float inv = 1.0f / (float)NN;
        float mu = g_bnsum[c] * inv;
        float var = g_bnsum[128 + c] * inv - mu * mu;
        float sc = gamma[c] * rsqrtf(var + 1e-5f);
        scoef[c] = sc;
        scoef[128 + c] = beta[c] - mu * sc;
    }
    __syncthreads();

    int gw = (blockIdx.x * blockDim.x + threadIdx.x) >> 5;
    if (gw >= NN) return;
    int lane = threadIdx.x & 31;
    float h[4];
    #pragma unroll
    for (int u = 0; u < 4; u++) {
        int c = lane + 32 * u;
        float v = z[gw * 128 + c];
        h[u] = fmaxf(v * scoef[c] + scoef[128 + c], 0.f);
    }
    float acc = (lane < 19) ? b[lane] : 0.f;
    #pragma unroll
    for (int u = 0; u < 4; u++) {
        #pragma unroll
        for (int l = 0; l < 32; l++) {
            float hb = __shfl_sync(0xffffffffu, h[u], l);
            if (lane < 19) acc += hb * __ldg(&W[(u * 32 + l) * 19 + lane]);
        }
    }
    float v = (lane < 19) ? acc : -3.4e38f;
    float m = v;
    #pragma unroll
    for (int off = 16; off > 0; off >>= 1) m = fmaxf(m, __shfl_xor_sync(0xffffffffu, m, off));
    float ex = (lane < 19) ? expf(v - m) : 0.f;
    float ssum = ex;
    #pragma unroll
    for (int off = 16; off > 0; off >>= 1) ssum += __shfl_xor_sync(0xffffffffu, ssum, off);
    if (lane < 19) out[gw * 19 + lane] = v - m - logf(ssum);
}

// ---------------------------------------------------------------------------
extern "C" void kernel_launch(void* const* d_in, const int* in_sizes, int n_in,
                              void* d_out, int out_size) {
    const float* x     = (const float*)d_in[0];
    const int*   ei    = (const int*)d_in[1];
    const float* W1    = (const float*)d_in[2];
    const float* b1    = (const float*)d_in[3];
    const float* W2    = (const float*)d_in[4];
    const float* b2    = (const float*)d_in[5];
    const float* W3    = (const float*)d_in[6];
    const float* b3    = (const float*)d_in[7];
    const float* fc1W  = (const float*)d_in[8];
    const float* fc1b  = (const float*)d_in[9];
    const float* fc2aW = (const float*)d_in[10];
    const float* fc2ab = (const float*)d_in[11];
    const float* gamma = (const float*)d_in[12];
    const float* beta  = (const float*)d_in[13];
    const float* fc2bW = (const float*)d_in[14];
    const float* fc2bb = (const float*)d_in[15];
    float* out = (float*)d_out;

    const int* src = ei;
    const int* dst = ei + EE;

    float* bufA;
    cudaGetSymbolAddress((void**)&bufA, g_bufA);
    __half *p0, *p1, *xh;
    cudaGetSymbolAddress((void**)&p0, g_p0);
    cudaGetSymbolAddress((void**)&p1, g_p1);
    cudaGetSymbolAddress((void**)&xh, g_xh);
    __half *w1h, *w2h, *w3h, *f1h, *f2h;
    cudaGetSymbolAddress((void**)&w1h, g_w1h);
    cudaGetSymbolAddress((void**)&w2h, g_w2h);
    cudaGetSymbolAddress((void**)&w3h, g_w3h);
    cudaGetSymbolAddress((void**)&f1h, g_f1h);
    cudaGetSymbolAddress((void**)&f2h, g_f2h);

    cudaFuncSetAttribute(k_mma<0>, cudaFuncAttributeMaxDynamicSharedMemorySize, 2 * BUFB);
    cudaFuncSetAttribute(k_mma<1>, cudaFuncAttributeMaxDynamicSharedMemorySize, 2 * BUFB);
    const size_t SMB = 2 * BUFB;   // 40960 bytes

    const int nb = (NN + 1023) / 1024;  // 98

    // CSR build (zeroes g_bnsum too); scan2 folded into rowptr
    k_zero<<<(NN + 255) / 256, 256>>>();
    k_count<<<(EE + 255) / 256, 256>>>(dst);
    k_scan1<<<nb, 1024>>>();
    k_rowptr<<<(NN + 255) / 256, 256>>>(nb);
    k_fill<<<(EE + 255) / 256, 256>>>(src, dst);

    // weight prep + x conversion in one launch (6 segments)
    k_prep_all<<<dim3(256, 6), 256>>>(W1, W2, W3, fc1W, fc2aW, x,
                                      w1h, w2h, w3h, f1h, f2h, xh);

    const int aggBlocks = (NN * 32 + 255) / 256;
    const int gy = (NN + 127) / 128;  // 782

    // conv1: agg(xh fp16) -> p0 ; mma -> p1 (fp16, ldc=128)
    k_agg16<<<aggBlocks, 256>>>(xh, p0);
    k_mma<0><<<dim3(1, gy), 256, SMB>>>(p0, w1h, b1, 0, p1, NN, 128, 100, 128, 1, 1);
    // conv2
    k_agg16<<<aggBlocks, 256>>>(p1, p0);
    k_mma<0><<<dim3(1, gy), 256, SMB>>>(p0, w2h, b2, 0, p1, NN, 128, 100, 128, 1, 1);
    // conv3 -> p1 (fp16, ldc=256)
    k_agg16<<<aggBlocks, 256>>>(p1, p0);
    k_mma<0><<<dim3(2, gy), 256, SMB>>>(p0, w3h, b3, 0, p1, NN, 128, 256, 256, 1, 1);
    // fc1 -> p0 (fp16, ldc=256)
    k_mma<0><<<dim3(2, gy), 256, SMB>>>(p1, f1h, fc1b, 0, p0, NN, 256, 256, 256, 1, 1);
    // fc2a -> fp32 bufA, fused BN statistics
    k_mma<1><<<dim3(1, gy), 256, SMB>>>(p0, f2h, fc2ab, bufA, 0, NN, 256, 128, 128, 0, 0);
    // final
    k_final_out<<<aggBlocks, 256>>>(bufA, gamma, beta, fc2bW, fc2bb, out);
}

// round 17
// speedup vs baseline: 1.0470x; 1.0321x over previous
#include <cuda_runtime.h>
#include <cuda_fp16.h>
#include <math.h>
#include <stdint.h>

#define NN 100000
#define EE 1600000
#define FIN 100

typedef unsigned long long ull;

// ---------------- scratch (static device allocations) ----------------
__device__ __align__(16) __half g_p0[NN * 256];
__device__ __align__(16) __half g_p1[NN * 256];
__device__ __align__(16) __half g_xh[NN * 128];
__device__ int   g_deg[NN];
__device__ int   g_incl[NN];
__device__ int   g_rowptr[NN + 1];
__device__ int   g_cursor[NN];
__device__ __align__(8) uint2 g_edge[EE];   // {src, norm(fp32 bits)}
__device__ float g_dinv[NN];
__device__ int   g_part[128];
__device__ float g_bnsum[256];
// transposed fp16 weights, [Npad][Kpad]
__device__ __align__(16) __half g_w1h[128 * 128];
__device__ __align__(16) __half g_w2h[128 * 128];
__device__ __align__(16) __half g_w3h[256 * 128];
__device__ __align__(16) __half g_f1h[256 * 256];
__device__ __align__(16) __half g_f2h[128 * 256];

// ---------------- PTX helpers ----------------
__device__ __forceinline__ uint32_t smem_u32(const void* p) {
    uint32_t a;
    asm("{ .reg .u64 t; cvta.to.shared.u64 t, %1; cvt.u32.u64 %0, t; }" : "=r"(a) : "l"(p));
    return a;
}
__device__ __forceinline__ void ldsm4(uint32_t addr, uint32_t* r) {
    asm volatile("ldmatrix.sync.aligned.m8n8.x4.shared.b16 {%0,%1,%2,%3}, [%4];"
                 : "=r"(r[0]), "=r"(r[1]), "=r"(r[2]), "=r"(r[3]) : "r"(addr));
}
__device__ __forceinline__ void mma16816(float* d, const uint32_t* a, const uint32_t* b) {
    asm volatile(
        "mma.sync.aligned.m16n8k16.row.col.f32.f16.f16.f32 "
        "{%0,%1,%2,%3}, {%4,%5,%6,%7}, {%8,%9}, {%0,%1,%2,%3};"
        : "+f"(d[0]), "+f"(d[1]), "+f"(d[2]), "+f"(d[3])
        : "r"(a[0]), "r"(a[1]), "r"(a[2]), "r"(a[3]), "r"(b[0]), "r"(b[1]));
}
__device__ __forceinline__ void cp16(uint32_t s, const void* g) {
    asm volatile("cp.async.cg.shared.global [%0], [%1], 16;" :: "r"(s), "l"(g));
}
__device__ __forceinline__ void cp16z(uint32_t s, const void* g, int srcsz) {
    asm volatile("cp.async.cg.shared.global [%0], [%1], 16, %2;" :: "r"(s), "l"(g), "r"(srcsz));
}
#define CP_COMMIT() asm volatile("cp.async.commit_group;" ::: "memory")
#define CP_WAIT(n)  asm volatile("cp.async.wait_group %0;" :: "n"(n) : "memory")

__device__ __forceinline__ uint32_t pack_h2(float a, float b) {
    __half2 h = __floats2half2_rn(a, b);
    return *reinterpret_cast<uint32_t*>(&h);
}

// ---------------- CSR build ----------------
__global__ void k_zero() {
    int i = blockIdx.x * blockDim.x + threadIdx.x;
    if (i < NN) g_deg[i] = 0;
    if (i < 256) g_bnsum[i] = 0.0f;
}
__global__ void k_count(const int* __restrict__ dst) {
    int e = blockIdx.x * blockDim.x + threadIdx.x;
    if (e < EE) atomicAdd(&g_deg[dst[e]], 1);
}
__global__ void k_scan1() {
    __shared__ int sh[1024];
    int i = blockIdx.x * 1024 + threadIdx.x;
    int v = (i < NN) ? g_deg[i] : 0;
    sh[threadIdx.x] = v;
    __syncthreads();
    for (int off = 1; off < 1024; off <<= 1) {
        int t = (threadIdx.x >= (unsigned)off) ? sh[threadIdx.x - off] : 0;
        __syncthreads();
        sh[threadIdx.x] += t;
        __syncthreads();
    }
    if (i < NN) g_incl[i] = sh[threadIdx.x];
    if (threadIdx.x == 1023) g_part[blockIdx.x] = sh[1023];
}
__global__ void k_scan2(int nb) {
    __shared__ int sh[128];
    int t = threadIdx.x;
    sh[t] = (t < nb) ? g_part[t] : 0;
    __syncthreads();
    for (int off = 1; off < 128; off <<= 1) {
        int u = (t >= off) ? sh[t - off] : 0;
        __syncthreads();
        sh[t] += u;
        __syncthreads();
    }
    g_part[t] = (t == 0) ? 0 : sh[t - 1];
}
__global__ void k_rowptr() {
    int i = blockIdx.x * blockDim.x + threadIdx.x;
    if (i >= NN) return;
    int excl = g_incl[i] - g_deg[i] + g_part[i >> 10];
    g_rowptr[i] = excl;
    g_cursor[i] = excl;
    g_dinv[i] = rsqrtf((float)g_deg[i] + 1.0f);
    if (i == NN - 1) g_rowptr[NN] = g_incl[i] + g_part[i >> 10];
}
__global__ void k_fill(const int* __restrict__ src, const int* __restrict__ dst) {
    int e = blockIdx.x * blockDim.x + threadIdx.x;
    if (e >= EE) return;
    int s = src[e], d = dst[e];
    int p = atomicAdd(&g_cursor[d], 1);
    float nr = __ldg(&g_dinv[s]) * __ldg(&g_dinv[d]);
    g_edge[p] = make_uint2((uint32_t)s, __float_as_uint(nr));
}

// -------- x -> clipped fp16 [.,128] ------------------------------------------
__global__ void k_xconv(const float* __restrict__ x, __half* __restrict__ oh) {
    int gw = (blockIdx.x * blockDim.x + threadIdx.x) >> 5;
    if (gw >= NN) return;
    int lane = threadIdx.x & 31;
    uint2 ph = {0u, 0u};
    if (lane < 25) {
        float4 v = __ldg((const float4*)(x + (size_t)gw * FIN + (lane << 2)));
        v.x = fminf(fmaxf(v.x, -0.4f), 0.4f);
        v.y = fminf(fmaxf(v.y, -0.4f), 0.4f);
        v.z = fminf(fmaxf(v.z, -0.4f), 0.4f);
        v.w = fminf(fmaxf(v.w, -0.4f), 0.4f);
        ph.x = pack_h2(v.x, v.y);
        ph.y = pack_h2(v.z, v.w);
    }
    ((uint2*)oh)[((size_t)gw << 5) + lane] = ph;
}

// -------- aggregation: fp16 in [.,128] -> fp16 out, packed edges -------------
__global__ void k_agg16(const __half* __restrict__ in, __half* __restrict__ oh) {
    int gw = (blockIdx.x * blockDim.x + threadIdx.x) >> 5;
    if (gw >= NN) return;
    int lane = threadIdx.x & 31;
    bool act = lane < 25;
    float di = g_dinv[gw];
    int s0 = g_rowptr[gw], s1 = g_rowptr[gw + 1];
    float a0 = 0.f, a1 = 0.f, a2 = 0.f, a3 = 0.f;
    float b0 = 0.f, b1 = 0.f, b2 = 0.f, b3 = 0.f;
    float c0 = 0.f, c1 = 0.f, c2 = 0.f, c3 = 0.f;
    float d0 = 0.f, d1 = 0.f, d2 = 0.f, d3 = 0.f;
    const uint2* inv = (const uint2*)in;
    int e = s0;
    for (; e + 3 < s1; e += 4) {
        uint2 e0 = __ldg(&g_edge[e]);
        uint2 e1 = __ldg(&g_edge[e + 1]);
        uint2 e2 = __ldg(&g_edge[e + 2]);
        uint2 e3 = __ldg(&g_edge[e + 3]);
        if (act) {
            uint2 u0 = __ldg(inv + ((size_t)e0.x << 5) + lane);
            uint2 u1 = __ldg(inv + ((size_t)e1.x << 5) + lane);
            uint2 u2 = __ldg(inv + ((size_t)e2.x << 5) + lane);
            uint2 u3 = __ldg(inv + ((size_t)e3.x << 5) + lane);
            float n0 = __uint_as_float(e0.y), n1 = __uint_as_float(e1.y);
            float n2 = __uint_as_float(e2.y), n3 = __uint_as_float(e3.y);
            float2 f;
            f = __half22float2(*(__half2*)&u0.x); a0 += n0 * f.x; a1 += n0 * f.y;
            f = __half22float2(*(__half2*)&u0.y); a2 += n0 * f.x; a3 += n0 * f.y;
            f = __half22float2(*(__half2*)&u1.x); b0 += n1 * f.x; b1 += n1 * f.y;
            f = __half22float2(*(__half2*)&u1.y); b2 += n1 * f.x; b3 += n1 * f.y;
            f = __half22float2(*(__half2*)&u2.x); c0 += n2 * f.x; c1 += n2 * f.y;
            f = __half22float2(*(__half2*)&u2.y); c2 += n2 * f.x; c3 += n2 * f.y;
            f = __half22float2(*(__half2*)&u3.x); d0 += n3 * f.x; d1 += n3 * f.y;
            f = __half22float2(*(__half2*)&u3.y); d2 += n3 * f.x; d3 += n3 * f.y;
        }
    }
    for (; e < s1; e++) {
        uint2 e0 = __ldg(&g_edge[e]);
        if (act) {
            uint2 u0 = __ldg(inv + ((size_t)e0.x << 5) + lane);
            float n0 = __uint_as_float(e0.y);
            float2 f;
            f = __half22float2(*(__half2*)&u0.x); a0 += n0 * f.x; a1 += n0 * f.y;
            f = __half22float2(*(__half2*)&u0.y); a2 += n0 * f.x; a3 += n0 * f.y;
        }
    }
    if (act) {   // self loop
        float nn = di * di;
        uint2 u = *(inv + ((size_t)gw << 5) + lane);
        float2 f0 = __half22float2(*(__half2*)&u.x);
        float2 f1 = __half22float2(*(__half2*)&u.y);
        a0 += nn * f0.x; a1 += nn * f0.y; a2 += nn * f1.x; a3 += nn * f1.y;
    }
    a0 += b0 + c0 + d0; a1 += b1 + c1 + d1;
    a2 += b2 + c2 + d2; a3 += b3 + c3 + d3;
    uint2 ph = {0u, 0u};
    if (act) { ph.x = pack_h2(a0, a1); ph.y = pack_h2(a2, a3); }
    ((uint2*)oh)[((size_t)gw << 5) + lane] = ph;
}

// ------- combined weight prep: 5 segments, single fp16 output ----------------
__global__ void k_prep_all(const float* W1, const float* W2, const float* W3,
                           const float* F1, const float* F2,
                           __half* w1h, __half* w2h, __half* w3h,
                           __half* f1h, __half* f2h) {
    int seg = blockIdx.y;
    const float* W; __half* Th;
    int K, Nw, Kpad, Npad;
    switch (seg) {
        case 0: W = W1; Th = w1h; K = 100; Nw = 100; Kpad = 128; Npad = 128; break;
        case 1: W = W2; Th = w2h; K = 100; Nw = 100; Kpad = 128; Npad = 128; break;
        case 2: W = W3; Th = w3h; K = 100; Nw = 256; Kpad = 128; Npad = 256; break;
        case 3: W = F1; Th = f1h; K = 256; Nw = 256; Kpad = 256; Npad = 256; break;
        default: W = F2; Th = f2h; K = 256; Nw = 128; Kpad = 256; Npad = 128; break;
    }
    int total = Npad * Kpad;
    for (int idx = blockIdx.x * blockDim.x + threadIdx.x; idx < total; idx += gridDim.x * blockDim.x) {
        int n = idx / Kpad, k = idx % Kpad;
        float v = (k < K && n < Nw) ? W[(size_t)k * Nw + n] : 0.f;
        Th[idx] = __float2half_rn(v);
    }
}

// ------- mma.sync fp16 GEMM, single product: C = act(A @ W + bias) ----------
#define LDW 20
#define CHB (128 * LDW * 4)
#define BUFB (2 * CHB)

template <int BNACC>
__global__ void __launch_bounds__(256, 2)
k_mma(const __half* __restrict__ A, const __half* __restrict__ Bh,
      const float* __restrict__ bias, __half* __restrict__ Ch,
      int M, int Kpad, int Nc, int ldc, int relu) {
    extern __shared__ uint32_t sm[];
    uint32_t sbase = smem_u32(sm);

    int tid = threadIdx.x;
    int wid = tid >> 5, lane = tid & 31;
    int br = blockIdx.y * 128;
    int bc = blockIdx.x * 128;
    int wm = (wid & 3) * 32;
    int wn = (wid >> 2) * 64;

    int srow[2], sg[2];
    uint32_t soff[2];
    #pragma unroll
    for (int j = 0; j < 2; j++) {
        int idx = tid + (j << 8);
        srow[j] = idx >> 2; sg[j] = idx & 3;
        soff[j] = (uint32_t)(srow[j] * LDW + (sg[j] << 2)) * 4;
    }

    uint32_t aOff[2], bOff[4];
    #pragma unroll
    for (int mt = 0; mt < 2; mt++)
        aOff[mt] = ((wm + mt * 16 + (lane & 15)) * 40 + ((lane >> 4) << 3)) * 2;
    #pragma unroll
    for (int ng = 0; ng < 4; ng++)
        bOff[ng] = ((wn + ng * 16 + (lane & 7) + ((lane >> 4) << 3)) * 40 + (((lane >> 3) & 1) << 3)) * 2;

    float acc[2][8][4];
    #pragma unroll
    for (int i = 0; i < 2; i++)
        #pragma unroll
        for (int j = 0; j < 8; j++)
            #pragma unroll
            for (int p = 0; p < 4; p++) acc[i][j][p] = 0.f;

    int nkc = Kpad >> 5;

    auto stage = [&](int kc, int buf) {
        int k0 = kc << 5;
        uint32_t b0 = sbase + buf * BUFB;
        #pragma unroll
        for (int j = 0; j < 2; j++) {
            int gm = br + srow[j];
            int ok = (gm < M);
            size_t ga = ((size_t)(ok ? gm : 0) * Kpad + k0) * 2 + (sg[j] << 4);
            cp16z(b0 + soff[j], (const char*)A + ga, ok ? 16 : 0);
            size_t gb = ((size_t)(bc + srow[j]) * Kpad + k0) * 2 + (sg[j] << 4);
            cp16(b0 + CHB + soff[j], (const char*)Bh + gb);
        }
    };

    stage(0, 0);
    CP_COMMIT();

    for (int kc = 0; kc < nkc; kc++) {
        int buf = kc & 1;
        if (kc + 1 < nkc) {
            stage(kc + 1, buf ^ 1);
            CP_COMMIT();
            CP_WAIT(1);
        } else {
            CP_WAIT(0);
        }
        __syncthreads();

        uint32_t aBase = sbase + buf * BUFB;
        uint32_t bBase = aBase + CHB;

        #pragma unroll
        for (int kk = 0; kk < 32; kk += 16) {
            uint32_t aF[2][4], bb[8][2];
            #pragma unroll
            for (int mt = 0; mt < 2; mt++) ldsm4(aBase + aOff[mt] + kk * 2, aF[mt]);
            #pragma unroll
            for (int ng = 0; ng < 4; ng++) ldsm4(bBase + bOff[ng] + kk * 2, &bb[2 * ng][0]);
            #pragma unroll
            for (int mt = 0; mt < 2; mt++)
                #pragma unroll
                for (int nt = 0; nt < 8; nt++) mma16816(acc[mt][nt], aF[mt], bb[nt]);
        }
        __syncthreads();
    }

    float sC[8][2], sQ[8][2];
    if (BNACC) {
        #pragma unroll
        for (int nt = 0; nt < 8; nt++) { sC[nt][0] = sC[nt][1] = sQ[nt][0] = sQ[nt][1] = 0.f; }
    }

    // ---- epilogue: fp16 padded output everywhere ----
    #pragma unroll
    for (int mt = 0; mt < 2; mt++) {
        int r0 = br + wm + mt * 16 + (lane >> 2);
        #pragma unroll
        for (int nt = 0; nt < 8; nt++) {
            int gn = bc + wn + nt * 8 + ((lane & 3) << 1);
            float bv0 = (gn < Nc) ? bias[gn] : 0.f;
            float bv1 = (gn + 1 < Nc) ? bias[gn + 1] : 0.f;
            float c0 = acc[mt][nt][0] + bv0, c1 = acc[mt][nt][1] + bv1;
            float c2 = acc[mt][nt][2] + bv0, c3 = acc[mt][nt][3] + bv1;
            if (relu) {
                c0 = fmaxf(c0, 0.f); c1 = fmaxf(c1, 0.f);
                c2 = fmaxf(c2, 0.f); c3 = fmaxf(c3, 0.f);
            }
            if (BNACC) {
                float v0 = (r0 < M) ? c0 : 0.f, v2 = (r0 + 8 < M) ? c2 : 0.f;
                float v1 = (r0 < M) ? c1 : 0.f, v3 = (r0 + 8 < M) ? c3 : 0.f;
                sC[nt][0] += v0 + v2; sQ[nt][0] += v0 * v0 + v2 * v2;
                sC[nt][1] += v1 + v3; sQ[nt][1] += v1 * v1 + v3 * v3;
            }
            if (r0 < M)
                ((uint32_t*)Ch)[((size_t)r0 * ldc + gn) >> 1] = pack_h2(c0, c1);
            if (r0 + 8 < M)
                ((uint32_t*)Ch)[((size_t)(r0 + 8) * ldc + gn) >> 1] = pack_h2(c2, c3);
        }
    }

    if (BNACC) {
        #pragma unroll
        for (int nt = 0; nt < 8; nt++) {
            #pragma unroll
            for (int c = 0; c < 2; c++) {
                float s = sC[nt][c], q = sQ[nt][c];
                #pragma unroll
                for (int off = 4; off < 32; off <<= 1) {
                    s += __shfl_xor_sync(0xffffffffu, s, off);
                    q += __shfl_xor_sync(0xffffffffu, q, off);
                }
                if ((lane >> 2) == 0) {
                    int gn = bc + wn + nt * 8 + ((lane & 3) << 1) + c;
                    atomicAdd(&g_bnsum[gn], s);
                    atomicAdd(&g_bnsum[128 + gn], q);
                }
            }
        }
    }
}

// ------- final: BN coef + affine + ReLU + [128x19] GEMV + log_softmax -------
// z is fp16 [NN][128]; lane owns cols 4*lane .. 4*lane+3
__global__ void k_final_out(const __half* __restrict__ z, const float* __restrict__ gamma,
                            const float* __restrict__ beta, const float* __restrict__ W,
                            const float* __restrict__ b, float* __restrict__ out) {
    __shared__ float scoef[256];
    if (threadIdx.x < 128) {
        int c = threadIdx.x;
        float inv = 1.0f / (float)NN;
        float mu = g_bnsum[c] * inv;
        float var = g_bnsum[128 + c] * inv - mu * mu;
        float sc = gamma[c] * rsqrtf(var + 1e-5f);
        scoef[c] = sc;
        scoef[128 + c] = beta[c] - mu * sc;
    }
    __syncthreads();

    int gw = (blockIdx.x * blockDim.x + threadIdx.x) >> 5;
    if (gw >= NN) return;
    int lane = threadIdx.x & 31;
    uint2 u = __ldg((const uint2*)z + ((size_t)gw << 5) + lane);
    float2 f0 = __half22float2(*(__half2*)&u.x);
    float2 f1 = __half22float2(*(__half2*)&u.y);
    float h[4] = {f0.x, f0.y, f1.x, f1.y};
    #pragma unroll
    for (int uu = 0; uu < 4; uu++) {
        int c = (lane << 2) + uu;
        h[uu] = fmaxf(h[uu] * scoef[c] + scoef[128 + c], 0.f);
    }
    float acc = (lane < 19) ? b[lane] : 0.f;
    #pragma unroll
    for (int uu = 0; uu < 4; uu++) {
        #pragma unroll
        for (int l = 0; l < 32; l++) {
            float hb = __shfl_sync(0xffffffffu, h[uu], l);
            if (lane < 19) acc += hb * __ldg(&W[((l << 2) + uu) * 19 + lane]);
        }
    }
    float v = (lane < 19) ? acc : -3.4e38f;
    float m = v;
    #pragma unroll
    for (int off = 16; off > 0; off >>= 1) m = fmaxf(m, __shfl_xor_sync(0xffffffffu, m, off));
    float ex = (lane < 19) ? expf(v - m) : 0.f;
    float ssum = ex;
    #pragma unroll
    for (int off = 16; off > 0; off >>= 1) ssum += __shfl_xor_sync(0xffffffffu, ssum, off);
    if (lane < 19) out[gw * 19 + lane] = v - m - logf(ssum);
}

// ---------------------------------------------------------------------------
extern "C" void kernel_launch(void* const* d_in, const int* in_sizes, int n_in,
                              void* d_out, int out_size) {
    const float* x     = (const float*)d_in[0];
    const int*   ei    = (const int*)d_in[1];
    const float* W1    = (const float*)d_in[2];
    const float* b1    = (const float*)d_in[3];
    const float* W2    = (const float*)d_in[4];
    const float* b2    = (const float*)d_in[5];
    const float* W3    = (const float*)d_in[6];
    const float* b3    = (const float*)d_in[7];
    const float* fc1W  = (const float*)d_in[8];
    const float* fc1b  = (const float*)d_in[9];
    const float* fc2aW = (const float*)d_in[10];
    const float* fc2ab = (const float*)d_in[11];
    const float* gamma = (const float*)d_in[12];
    const float* beta  = (const float*)d_in[13];
    const float* fc2bW = (const float*)d_in[14];
    const float* fc2bb = (const float*)d_in[15];
    float* out = (float*)d_out;

    const int* src = ei;
    const int* dst = ei + EE;

    __half *p0, *p1, *xh;
    cudaGetSymbolAddress((void**)&p0, g_p0);
    cudaGetSymbolAddress((void**)&p1, g_p1);
    cudaGetSymbolAddress((void**)&xh, g_xh);
    __half *w1h, *w2h, *w3h, *f1h, *f2h;
    cudaGetSymbolAddress((void**)&w1h, g_w1h);
    cudaGetSymbolAddress((void**)&w2h, g_w2h);
    cudaGetSymbolAddress((void**)&w3h, g_w3h);
    cudaGetSymbolAddress((void**)&f1h, g_f1h);
    cudaGetSymbolAddress((void**)&f2h, g_f2h);

    cudaFuncSetAttribute(k_mma<0>, cudaFuncAttributeMaxDynamicSharedMemorySize, 2 * BUFB);
    cudaFuncSetAttribute(k_mma<1>, cudaFuncAttributeMaxDynamicSharedMemorySize, 2 * BUFB);
    const size_t SMB = 2 * BUFB;   // 40960 bytes

    const int nb = (NN + 1023) / 1024;  // 98

    // CSR build (zeroes g_bnsum too)
    k_zero<<<(NN + 255) / 256, 256>>>();
    k_count<<<(EE + 255) / 256, 256>>>(dst);
    k_scan1<<<nb, 1024>>>();
    k_scan2<<<1, 128>>>(nb);
    k_rowptr<<<(NN + 255) / 256, 256>>>();
    k_fill<<<(EE + 255) / 256, 256>>>(src, dst);

    // weight prep (one launch, 5 segments) + x conversion
    k_prep_all<<<dim3(64, 5), 256>>>(W1, W2, W3, fc1W, fc2aW, w1h, w2h, w3h, f1h, f2h);
    const int aggBlocks = (NN * 32 + 255) / 256;
    k_xconv<<<aggBlocks, 256>>>(x, xh);

    const int gy = (NN + 127) / 128;  // 782

    // conv1: agg(xh) -> p0 ; mma -> p1 (fp16, ldc=128)
    k_agg16<<<aggBlocks, 256>>>(xh, p0);
    k_mma<0><<<dim3(1, gy), 256, SMB>>>(p0, w1h, b1, p1, NN, 128, 100, 128, 1);
    // conv2
    k_agg16<<<aggBlocks, 256>>>(p1, p0);
    k_mma<0><<<dim3(1, gy), 256, SMB>>>(p0, w2h, b2, p1, NN, 128, 100, 128, 1);
    // conv3 -> p1 (fp16, ldc=256)
    k_agg16<<<aggBlocks, 256>>>(p1, p0);
    k_mma<0><<<dim3(2, gy), 256, SMB>>>(p0, w3h, b3, p1, NN, 128, 256, 256, 1);
    // fc1 -> p0 (fp16, ldc=256)
    k_mma<0><<<dim3(2, gy), 256, SMB>>>(p1, f1h, fc1b, p0, NN, 256, 256, 256, 1);
    // fc2a -> fp16 z (reuse p1, ldc=128), fused BN statistics (fp32 accumulators)
    k_mma<1><<<dim3(1, gy), 256, SMB>>>(p0, f2h, fc2ab, p1, NN, 256, 128, 128, 0);
    // final: BN coef in-kernel + affine (fp16 z) + GEMV + log_softmax
    k_final_out<<<aggBlocks, 256>>>(p1, gamma, beta, fc2bW, fc2bb, out);
}